// round 8
// baseline (speedup 1.0000x reference)
#include <cuda_runtime.h>
#include <cstdint>

// GraphNetBlock — mma.sync tf32, v6:
//  * 3 CTAs/SM (smem 71KB, launch_bounds(256,3)): 24 warps/SM for latency hiding
//  * TE=64 rows/CTA, 4x2 warp grid, 16x64 warp tiles (c regs 32/thread)
//  * paired-k W smem layout (float2 {W[k][n],W[k+4][n]}): B = 8 LDS.64 per k8
//  * proj trick (45 GFLOP), W register-prefetch, red.v2 scatter, __stcs stores

#define H 128
#define TE 64
#define KC 32
#define THREADS 256

// float offsets in dynamic smem
#define SW_OFF 0                 // 2 x (16 x 132 float2) = 2 x 4224 floats
#define HA_OFF 8448              // A/hidden: 64 x 132 = 8448
#define BIAS_F 16896             // 5 x 128
#define STAT_F 17536             // sum[64], sq[64]
#define SSR_F  17664             // sS[64], sR[64] ints
#define SMEM_FLOATS 17792
#define SMEM_BYTES (SMEM_FLOATS * 4)   // 71168

__device__ float g_acc[50000 * H];
__device__ float g_proj[50000 * 384];

__device__ __forceinline__ float to_tf32(float x) {
    unsigned u;
    asm("cvt.rna.tf32.f32 %0, %1;" : "=r"(u) : "f"(x));
    return __uint_as_float(u);
}
__device__ __forceinline__ void mma8(float c[4], const unsigned a[4], unsigned b0, unsigned b1) {
    asm volatile(
        "mma.sync.aligned.m16n8k8.row.col.f32.tf32.tf32.f32 "
        "{%0,%1,%2,%3}, {%4,%5,%6,%7}, {%8,%9}, {%0,%1,%2,%3};"
        : "+f"(c[0]), "+f"(c[1]), "+f"(c[2]), "+f"(c[3])
        : "r"(a[0]), "r"(a[1]), "r"(a[2]), "r"(a[3]), "r"(b0), "r"(b1));
}
__device__ __forceinline__ void red2(float* p, float a, float b) {
    asm volatile("red.global.add.v2.f32 [%0], {%1, %2};" :: "l"(p), "f"(a), "f"(b) : "memory");
}

// one staged 32-k chunk: A stride 132 (rows wm*16..+16), W paired-k float2 rows
__device__ __forceinline__ void mma_chunk(float c[8][4], const float* As, const float* Ws,
                                          int wm, int wn, int g, int tig) {
#pragma unroll
    for (int k8 = 0; k8 < 4; k8++) {
        const float2* bp = (const float2*)Ws + (k8 * 4 + tig) * 132 + wn * 64 + g;
        float2 bv[8];
#pragma unroll
        for (int jj = 0; jj < 8; jj++) bv[jj] = bp[jj * 8];
        unsigned a[4];
        const float* ap = As + (wm * 16 + g) * 132 + k8 * 8 + tig;
        a[0] = __float_as_uint(ap[0]);
        a[1] = __float_as_uint(ap[8 * 132]);
        a[2] = __float_as_uint(ap[4]);
        a[3] = __float_as_uint(ap[8 * 132 + 4]);
#pragma unroll
        for (int jj = 0; jj < 8; jj++)
            mma8(c[jj], a, __float_as_uint(bv[jj].x), __float_as_uint(bv[jj].y));
    }
}

// W staging: global [k][n] -> paired-k float2 layout. 4 LDG.128 + 4 STS.128 /thread.
__device__ __forceinline__ void ldg_W(float4 wv[4], const float* __restrict__ W, int kt, int tid) {
#pragma unroll
    for (int i = 0; i < 2; i++) {
        int idx = tid + (i << 8);           // 0..511
        int kp = idx >> 5;                  // 0..15
        int n0 = (idx & 31) << 2;
        int klo = kt + (kp >> 2) * 8 + (kp & 3);
        wv[2 * i]     = *(const float4*)(W + (size_t)klo * H + n0);
        wv[2 * i + 1] = *(const float4*)(W + (size_t)(klo + 4) * H + n0);
    }
}
__device__ __forceinline__ void sts_W(const float4 wv[4], float* sWd, int tid) {
#pragma unroll
    for (int i = 0; i < 2; i++) {
        int idx = tid + (i << 8);
        int kp = idx >> 5;
        int n0 = (idx & 31) << 2;
        float4 lo = wv[2 * i], hi = wv[2 * i + 1];
        *(float4*)(sWd + kp * 264 + n0 * 2) =
            make_float4(to_tf32(lo.x), to_tf32(hi.x), to_tf32(lo.y), to_tf32(hi.y));
        *(float4*)(sWd + kp * 264 + n0 * 2 + 4) =
            make_float4(to_tf32(lo.z), to_tf32(hi.z), to_tf32(lo.w), to_tf32(hi.w));
    }
}
__device__ __forceinline__ void zero_c(float c[8][4]) {
#pragma unroll
    for (int j = 0; j < 8; j++)
#pragma unroll
        for (int i = 0; i < 4; i++) c[j][i] = 0.f;
}

// ================= unified kernel: MODE 0=proj, 1=edge, 2=node =================
template <int MODE>
__global__ void __launch_bounds__(THREADS, 3)
gnb_kernel(const int* __restrict__ send, const int* __restrict__ recv,
           const float* __restrict__ nodef, const float* __restrict__ resid,
           float* __restrict__ acc, float* __restrict__ proj,
           const float* __restrict__ Wa, const float* __restrict__ Wb,
           const float* __restrict__ Wc,
           const float* __restrict__ pb0, const float* __restrict__ pb1,
           const float* __restrict__ pb2,
           const float* __restrict__ gam, const float* __restrict__ bet,
           float* __restrict__ out, int rows) {
    extern __shared__ float sm[];
    float* sW = sm + SW_OFF;
    float* hA = sm + HA_OFF;
    float* sSum = sm + STAT_F;
    float* sSq  = sm + STAT_F + 64;
    int* sS = (int*)(sm + SSR_F);
    int* sR = (int*)(sm + SSR_F + 64);

    const int tid = threadIdx.x, lane = tid & 31, warp = tid >> 5;
    const int g = lane >> 2, tig = lane & 3;
    const int wm = warp >> 1, wn = warp & 1;     // 4x2 warp grid, 16x64 tiles
    const int base = blockIdx.x * TE;
    const int nvalid = min(TE, rows - base);

    // ---- prologue ----
    if (MODE != 0 && tid < H) {
        sm[BIAS_F + 0 * H + tid] = pb0[tid];
        sm[BIAS_F + 1 * H + tid] = pb1[tid];
        sm[BIAS_F + 2 * H + tid] = pb2[tid];
        sm[BIAS_F + 3 * H + tid] = gam[tid];
        sm[BIAS_F + 4 * H + tid] = bet[tid];
    }
    if (MODE != 0 && tid < 64) { sSum[tid] = 0.f; sSq[tid] = 0.f; }
    if (MODE == 1 && tid < TE) {
        int e = min(base + tid, rows - 1);
        sS[tid] = send[e];
        sR[tid] = recv[e];
    }
    // stage A tile (64 x 128, tf32, stride 132)
#pragma unroll
    for (int i = 0; i < 8; i++) {
        int idx4 = tid + (i << 8);
        int r = idx4 >> 5;
        int c4 = (idx4 & 31) << 2;
        int rg = min(base + r, rows - 1);
        float4 v;
        if (MODE == 0) {
            v = *(const float4*)(nodef + (size_t)rg * H + c4);
        } else if (MODE == 1) {
            v = *(const float4*)(resid + (size_t)rg * H + c4);
        } else {
            float4* zp = (float4*)(acc + (size_t)rg * H + c4);
            v = *zp;
            if (base + r < rows) *zp = make_float4(0.f, 0.f, 0.f, 0.f);
        }
        *(float4*)(hA + r * 132 + c4) =
            make_float4(to_tf32(v.x), to_tf32(v.y), to_tf32(v.z), to_tf32(v.w));
    }

    float c[8][4];

#pragma unroll 1
    for (int s = 0; s < 3; s++) {
        const float* W = (s == 0) ? Wa : (s == 1) ? Wb : Wc;
        zero_c(c);
        float4 wv[4];
        ldg_W(wv, W, 0, tid);
        sts_W(wv, sW, tid);
        __syncthreads();   // W chunk0 staged; hA writes (prologue/epilogue) visible
#pragma unroll 1
        for (int t = 0; t < 4; t++) {
            if (t < 3) ldg_W(wv, W, (t + 1) * KC, tid);
            mma_chunk(c, hA + t * KC, sW + (t & 1) * 4224, wm, wn, g, tig);
            if (t < 3) sts_W(wv, sW + ((t + 1) & 1) * 4224, tid);
            __syncthreads();
        }

        // ================= epilogues =================
        if (MODE == 0) {
            // store raw to proj col-block s
#pragma unroll
            for (int h = 0; h < 2; h++) {
                int r = wm * 16 + g + 8 * h;
                if (r < nvalid) {
                    float* p = proj + (size_t)(base + r) * 384 + s * 128;
#pragma unroll
                    for (int jj = 0; jj < 8; jj++) {
                        int n0 = wn * 64 + jj * 8 + 2 * tig;
                        *(float2*)(p + n0) = make_float2(c[jj][2 * h], c[jj][2 * h + 1]);
                    }
                }
            }
        } else if (s == 0) {
            const float* bS = sm + BIAS_F;
#pragma unroll
            for (int h = 0; h < 2; h++) {
                int r = wm * 16 + g + 8 * h;
                const float* sp;
                const float* rp = nullptr;
                if (MODE == 1) {
                    sp = proj + (size_t)sS[r] * 384;
                    rp = proj + (size_t)sR[r] * 384 + 128;
                } else {
                    sp = proj + (size_t)min(base + r, rows - 1) * 384 + 256;
                }
#pragma unroll
                for (int jj = 0; jj < 8; jj++) {
                    int n0 = wn * 64 + jj * 8 + 2 * tig;
                    float2 av = *(const float2*)(sp + n0);
                    float v0 = c[jj][2 * h] + av.x + bS[n0];
                    float v1 = c[jj][2 * h + 1] + av.y + bS[n0 + 1];
                    if (MODE == 1) {
                        float2 bv = *(const float2*)(rp + n0);
                        v0 += bv.x;
                        v1 += bv.y;
                    }
                    *(float2*)(hA + r * 132 + n0) =
                        make_float2(to_tf32(fmaxf(v0, 0.f)), to_tf32(fmaxf(v1, 0.f)));
                }
            }
        } else if (s == 1) {
            const float* bS = sm + BIAS_F + H;
#pragma unroll
            for (int h = 0; h < 2; h++) {
                int r = wm * 16 + g + 8 * h;
#pragma unroll
                for (int jj = 0; jj < 8; jj++) {
                    int n0 = wn * 64 + jj * 8 + 2 * tig;
                    float v0 = c[jj][2 * h] + bS[n0];
                    float v1 = c[jj][2 * h + 1] + bS[n0 + 1];
                    *(float2*)(hA + r * 132 + n0) =
                        make_float2(to_tf32(fmaxf(v0, 0.f)), to_tf32(fmaxf(v1, 0.f)));
                }
            }
        } else {
            // ---- final: bias + LN (2-warp row combine) + residual + scatter ----
            const float* bS = sm + BIAS_F + 2 * H;
            float ps[2], pq[2];
#pragma unroll
            for (int h = 0; h < 2; h++) {
                float sacc = 0.f, qacc = 0.f;
#pragma unroll
                for (int jj = 0; jj < 8; jj++) {
                    int n0 = wn * 64 + jj * 8 + 2 * tig;
                    float v0 = c[jj][2 * h] + bS[n0];
                    float v1 = c[jj][2 * h + 1] + bS[n0 + 1];
                    c[jj][2 * h] = v0;
                    c[jj][2 * h + 1] = v1;
                    sacc += v0 + v1;
                    qacc += v0 * v0 + v1 * v1;
                }
                ps[h] = sacc;
                pq[h] = qacc;
            }
#pragma unroll
            for (int m = 1; m < 4; m <<= 1)
#pragma unroll
                for (int h = 0; h < 2; h++) {
                    ps[h] += __shfl_xor_sync(0xffffffffu, ps[h], m);
                    pq[h] += __shfl_xor_sync(0xffffffffu, pq[h], m);
                }
            if (tig == 0) {
#pragma unroll
                for (int h = 0; h < 2; h++) {
                    int r = wm * 16 + g + 8 * h;
                    atomicAdd(&sSum[r], ps[h]);
                    atomicAdd(&sSq[r], pq[h]);
                }
            }
            __syncthreads();
            const float* gS = sm + BIAS_F + 3 * H;
            const float* eS = sm + BIAS_F + 4 * H;
#pragma unroll
            for (int h = 0; h < 2; h++) {
                int r = wm * 16 + g + 8 * h;
                if (r >= nvalid) continue;
                float mu = sSum[r] * (1.f / H);
                float rs = rsqrtf(sSq[r] * (1.f / H) - mu * mu + 1e-5f);
                size_t ro = (size_t)(base + r) * H;
                int rc = (MODE == 1) ? sR[r] : 0;
#pragma unroll
                for (int jj = 0; jj < 8; jj++) {
                    int n0 = wn * 64 + jj * 8 + 2 * tig;
                    float y0 = (c[jj][2 * h] - mu) * rs * gS[n0] + eS[n0];
                    float y1 = (c[jj][2 * h + 1] - mu) * rs * gS[n0 + 1] + eS[n0 + 1];
                    float2 rf = *(const float2*)(resid + ro + n0);
                    __stcs((float2*)(out + ro + n0), make_float2(y0 + rf.x, y1 + rf.y));
                    if (MODE == 1) red2(&acc[(size_t)rc * H + n0], y0, y1);
                }
            }
        }
    }
}

// ============================ LAUNCH ============================
extern "C" void kernel_launch(void* const* d_in, const int* in_sizes, int n_in,
                              void* d_out, int out_size) {
    const int*   senders   = (const int*)d_in[0];
    const int*   receivers = (const int*)d_in[1];
    const float* nodef     = (const float*)d_in[2];
    const float* edgef     = (const float*)d_in[3];
    const float* eW0 = (const float*)d_in[4];
    const float* eb0 = (const float*)d_in[5];
    const float* eW1 = (const float*)d_in[6];
    const float* eb1 = (const float*)d_in[7];
    const float* eW2 = (const float*)d_in[8];
    const float* eb2 = (const float*)d_in[9];
    const float* eg  = (const float*)d_in[10];
    const float* ebeta = (const float*)d_in[11];
    const float* nW0 = (const float*)d_in[12];
    const float* nb0 = (const float*)d_in[13];
    const float* nW1 = (const float*)d_in[14];
    const float* nb1 = (const float*)d_in[15];
    const float* nW2 = (const float*)d_in[16];
    const float* nb2 = (const float*)d_in[17];
    const float* ng  = (const float*)d_in[18];
    const float* nbeta = (const float*)d_in[19];

    int E = in_sizes[1];
    int N = in_sizes[2] / H;

    float* out_node = (float*)d_out;
    float* out_edge = out_node + (size_t)N * H;

    float *acc = nullptr, *proj = nullptr;
    cudaGetSymbolAddress((void**)&acc, g_acc);
    cudaGetSymbolAddress((void**)&proj, g_proj);

    cudaFuncSetAttribute(gnb_kernel<0>, cudaFuncAttributeMaxDynamicSharedMemorySize, SMEM_BYTES);
    cudaFuncSetAttribute(gnb_kernel<1>, cudaFuncAttributeMaxDynamicSharedMemorySize, SMEM_BYTES);
    cudaFuncSetAttribute(gnb_kernel<2>, cudaFuncAttributeMaxDynamicSharedMemorySize, SMEM_BYTES);

    int ngrid = (N + TE - 1) / TE;
    int egrid = (E + TE - 1) / TE;

    // proj: P = nodef @ [eW0_send | eW0_recv | nW0_top]
    gnb_kernel<0><<<ngrid, THREADS, SMEM_BYTES>>>(
        nullptr, nullptr, nodef, nullptr, acc, proj,
        eW0, eW0 + (size_t)128 * H, nW0,
        eb0, eb0, eb0, eg, ebeta, nullptr, N);

    // edge MLP: ef @ eW0_bot (+gathered P) -> eW1 -> eW2 -> LN -> scatter
    gnb_kernel<1><<<egrid, THREADS, SMEM_BYTES>>>(
        senders, receivers, nodef, edgef, acc, proj,
        eW0 + (size_t)256 * H, eW1, eW2,
        eb0, eb1, eb2, eg, ebeta, out_edge, E);

    // node MLP: acc @ nW0_bot (+P nf-block) -> nW1 -> nW2 -> LN
    gnb_kernel<2><<<ngrid, THREADS, SMEM_BYTES>>>(
        nullptr, nullptr, nodef, nodef, acc, proj,
        nW0 + (size_t)128 * H, nW1, nW2,
        nb0, nb1, nb2, ng, nbeta, out_node, N);
}

// round 9
// speedup vs baseline: 1.2062x; 1.2062x over previous
#include <cuda_runtime.h>
#include <cstdint>

// GraphNetBlock — mma.sync tf32, v7 = v5 (782us) + packed-B LDS.128:
//  * W smem in permuted pair layout: per k8 a warp reads its B fragments with
//    4 LDS.128 (was 16 LDS.32). Same bytes, 1/4 the issues. Stride 260 -> 
//    conflict-free phases.
//  * otherwise identical to v5: proj trick, TE=128, 2 CTAs/SM, 32x64 tiles,
//    W register-prefetch, red.v2 scatter, __stcs stores

#define H 128
#define TE 128
#define KC 32
#define THREADS 256

// float offsets in dynamic smem
#define SWSTRIDE 260             // k-quad row stride (floats), 16B aligned, bank-safe
#define SWBUF 4160               // 16 rows x 260
#define SW_OFF 0                 // 2 x SWBUF = 8320
#define HA_OFF 8320              // A/hidden: 128 x 132 = 16896
#define BIAS_F 25216             // 5 x 128
#define STAT_F 25856             // sum[128], sq[128]
#define SSR_F  26112             // sS[128], sR[128] ints
#define SMEM_FLOATS 26368
#define SMEM_BYTES (SMEM_FLOATS * 4)   // 105472

__device__ float g_acc[50000 * H];
__device__ float g_proj[50000 * 384];

__device__ __forceinline__ float to_tf32(float x) {
    unsigned u;
    asm("cvt.rna.tf32.f32 %0, %1;" : "=r"(u) : "f"(x));
    return __uint_as_float(u);
}
__device__ __forceinline__ void mma8(float c[4], const unsigned a[4], unsigned b0, unsigned b1) {
    asm volatile(
        "mma.sync.aligned.m16n8k8.row.col.f32.tf32.tf32.f32 "
        "{%0,%1,%2,%3}, {%4,%5,%6,%7}, {%8,%9}, {%0,%1,%2,%3};"
        : "+f"(c[0]), "+f"(c[1]), "+f"(c[2]), "+f"(c[3])
        : "r"(a[0]), "r"(a[1]), "r"(a[2]), "r"(a[3]), "r"(b0), "r"(b1));
}
__device__ __forceinline__ void red2(float* p, float a, float b) {
    asm volatile("red.global.add.v2.f32 [%0], {%1, %2};" :: "l"(p), "f"(a), "f"(b) : "memory");
}

// one staged 32-k chunk: A stride 132 (rows wm*32..+32), W packed-pair layout.
// B fragment read: float4 {b0[jj],b1[jj],b0[jj+1],b1[jj+1]} at
//   (k8*4+tig)*260 + wn*128 + g*16 + jj*2
__device__ __forceinline__ void mma_chunk(float c[16][4], const float* As, const float* Ws,
                                          int wm, int wn, int g, int tig) {
#pragma unroll
    for (int k8 = 0; k8 < 4; k8++) {
        const float4* bp = (const float4*)(Ws + (k8 * 4 + tig) * SWSTRIDE + wn * 128 + g * 16);
        float4 bq[4];
#pragma unroll
        for (int q = 0; q < 4; q++) bq[q] = bp[q];
        unsigned a0[4], a1[4];
        {
            const float* ap = As + (wm * 32 + g) * 132 + k8 * 8 + tig;
            a0[0] = __float_as_uint(ap[0]);
            a0[1] = __float_as_uint(ap[8 * 132]);
            a0[2] = __float_as_uint(ap[4]);
            a0[3] = __float_as_uint(ap[8 * 132 + 4]);
            a1[0] = __float_as_uint(ap[16 * 132]);
            a1[1] = __float_as_uint(ap[24 * 132]);
            a1[2] = __float_as_uint(ap[16 * 132 + 4]);
            a1[3] = __float_as_uint(ap[24 * 132 + 4]);
        }
#pragma unroll
        for (int q = 0; q < 4; q++) {
            mma8(c[2 * q],     a0, __float_as_uint(bq[q].x), __float_as_uint(bq[q].y));
            mma8(c[2 * q + 1], a0, __float_as_uint(bq[q].z), __float_as_uint(bq[q].w));
            mma8(c[8 + 2 * q],     a1, __float_as_uint(bq[q].x), __float_as_uint(bq[q].y));
            mma8(c[8 + 2 * q + 1], a1, __float_as_uint(bq[q].z), __float_as_uint(bq[q].w));
        }
    }
}

// W staging: global [k][n] -> packed pair layout. LDG half / STS half.
__device__ __forceinline__ void ldg_W(float4 wv[4], const float* __restrict__ W, int kt, int tid) {
#pragma unroll
    for (int i = 0; i < 2; i++) {
        int idx = tid + (i << 8);           // 0..511
        int kp = idx >> 5;                  // k-quad row 0..15
        int n0 = (idx & 31) << 2;
        int klo = kt + (kp >> 2) * 8 + (kp & 3);
        wv[2 * i]     = *(const float4*)(W + (size_t)klo * H + n0);
        wv[2 * i + 1] = *(const float4*)(W + (size_t)(klo + 4) * H + n0);
    }
}
__device__ __forceinline__ void sts_W(const float4 wv[4], float* sWd, int tid) {
#pragma unroll
    for (int i = 0; i < 2; i++) {
        int idx = tid + (i << 8);
        int kp = idx >> 5;
        int n0 = (idx & 31) << 2;
        float lo[4] = {wv[2 * i].x, wv[2 * i].y, wv[2 * i].z, wv[2 * i].w};
        float hi[4] = {wv[2 * i + 1].x, wv[2 * i + 1].y, wv[2 * i + 1].z, wv[2 * i + 1].w};
#pragma unroll
        for (int u = 0; u < 4; u++) {
            int n = n0 + u;
            int gg = n & 7, jj = (n >> 3) & 7, wnb = n >> 6;
            *(float2*)(sWd + kp * SWSTRIDE + wnb * 128 + gg * 16 + jj * 2) =
                make_float2(to_tf32(lo[u]), to_tf32(hi[u]));
        }
    }
}
__device__ __forceinline__ void zero_c(float c[16][4]) {
#pragma unroll
    for (int j = 0; j < 16; j++)
#pragma unroll
        for (int i = 0; i < 4; i++) c[j][i] = 0.f;
}

// ================= unified kernel: MODE 0=proj, 1=edge, 2=node =================
template <int MODE>
__global__ void __launch_bounds__(THREADS, 2)
gnb_kernel(const int* __restrict__ send, const int* __restrict__ recv,
           const float* __restrict__ nodef, const float* __restrict__ resid,
           float* __restrict__ acc, float* __restrict__ proj,
           const float* __restrict__ Wa, const float* __restrict__ Wb,
           const float* __restrict__ Wc,
           const float* __restrict__ pb0, const float* __restrict__ pb1,
           const float* __restrict__ pb2,
           const float* __restrict__ gam, const float* __restrict__ bet,
           float* __restrict__ out, int rows) {
    extern __shared__ float sm[];
    float* sW = sm + SW_OFF;
    float* hA = sm + HA_OFF;
    float* sSum = sm + STAT_F;
    float* sSq  = sm + STAT_F + 128;
    int* sS = (int*)(sm + SSR_F);
    int* sR = (int*)(sm + SSR_F + 128);

    const int tid = threadIdx.x, lane = tid & 31, warp = tid >> 5;
    const int g = lane >> 2, tig = lane & 3;
    const int wm = warp >> 1, wn = warp & 1;
    const int base = blockIdx.x * TE;
    const int nvalid = min(TE, rows - base);

    // ---- prologue ----
    if (MODE != 0 && tid < H) {
        sm[BIAS_F + 0 * H + tid] = pb0[tid];
        sm[BIAS_F + 1 * H + tid] = pb1[tid];
        sm[BIAS_F + 2 * H + tid] = pb2[tid];
        sm[BIAS_F + 3 * H + tid] = gam[tid];
        sm[BIAS_F + 4 * H + tid] = bet[tid];
    }
    if (MODE != 0 && tid < 128) { sSum[tid] = 0.f; sSq[tid] = 0.f; }
    if (MODE == 1 && tid < TE) {
        int e = min(base + tid, rows - 1);
        sS[tid] = send[e];
        sR[tid] = recv[e];
    }
    // stage A tile (128 x 128, tf32, stride 132)
#pragma unroll
    for (int i = 0; i < 16; i++) {
        int idx4 = tid + (i << 8);
        int r = idx4 >> 5;
        int c4 = (idx4 & 31) << 2;
        int rg = min(base + r, rows - 1);
        float4 v;
        if (MODE == 0) {
            v = *(const float4*)(nodef + (size_t)rg * H + c4);
        } else if (MODE == 1) {
            v = *(const float4*)(resid + (size_t)rg * H + c4);
        } else {
            float4* zp = (float4*)(acc + (size_t)rg * H + c4);
            v = *zp;
            if (base + r < rows) *zp = make_float4(0.f, 0.f, 0.f, 0.f);
        }
        *(float4*)(hA + r * 132 + c4) =
            make_float4(to_tf32(v.x), to_tf32(v.y), to_tf32(v.z), to_tf32(v.w));
    }

    float c[16][4];

#pragma unroll 1
    for (int s = 0; s < 3; s++) {
        const float* W = (s == 0) ? Wa : (s == 1) ? Wb : Wc;
        zero_c(c);
        float4 wv[4];
        ldg_W(wv, W, 0, tid);
        sts_W(wv, sW, tid);
        __syncthreads();   // W chunk0 staged; hA writes (prologue/epilogue) visible
#pragma unroll 1
        for (int t = 0; t < 4; t++) {
            if (t < 3) ldg_W(wv, W, (t + 1) * KC, tid);
            mma_chunk(c, hA + t * KC, sW + (t & 1) * SWBUF, wm, wn, g, tig);
            if (t < 3) sts_W(wv, sW + ((t + 1) & 1) * SWBUF, tid);
            __syncthreads();
        }

        // ================= epilogues =================
        // c layout: c[2*q + (jj&1) + 8*mt] for jj = 2q+(0,1); n0 = wn*64 + jj*8 + 2*tig
        if (MODE == 0) {
#pragma unroll
            for (int mt = 0; mt < 2; mt++)
#pragma unroll
                for (int h = 0; h < 2; h++) {
                    int r = wm * 32 + mt * 16 + g + 8 * h;
                    if (r < nvalid) {
                        float* p = proj + (size_t)(base + r) * 384 + s * 128;
#pragma unroll
                        for (int jj = 0; jj < 8; jj++) {
                            int n0 = wn * 64 + jj * 8 + 2 * tig;
                            *(float2*)(p + n0) =
                                make_float2(c[mt * 8 + jj][2 * h], c[mt * 8 + jj][2 * h + 1]);
                        }
                    }
                }
        } else if (s == 0) {
            const float* bS = sm + BIAS_F;
#pragma unroll
            for (int mt = 0; mt < 2; mt++)
#pragma unroll
                for (int h = 0; h < 2; h++) {
                    int r = wm * 32 + mt * 16 + g + 8 * h;
                    const float* sp;
                    const float* rp = nullptr;
                    if (MODE == 1) {
                        sp = proj + (size_t)sS[r] * 384;
                        rp = proj + (size_t)sR[r] * 384 + 128;
                    } else {
                        sp = proj + (size_t)min(base + r, rows - 1) * 384 + 256;
                    }
#pragma unroll
                    for (int jj = 0; jj < 8; jj++) {
                        int n0 = wn * 64 + jj * 8 + 2 * tig;
                        float2 av = *(const float2*)(sp + n0);
                        float v0 = c[mt * 8 + jj][2 * h] + av.x + bS[n0];
                        float v1 = c[mt * 8 + jj][2 * h + 1] + av.y + bS[n0 + 1];
                        if (MODE == 1) {
                            float2 bv = *(const float2*)(rp + n0);
                            v0 += bv.x;
                            v1 += bv.y;
                        }
                        *(float2*)(hA + r * 132 + n0) =
                            make_float2(to_tf32(fmaxf(v0, 0.f)), to_tf32(fmaxf(v1, 0.f)));
                    }
                }
        } else if (s == 1) {
            const float* bS = sm + BIAS_F + H;
#pragma unroll
            for (int mt = 0; mt < 2; mt++)
#pragma unroll
                for (int h = 0; h < 2; h++) {
                    int r = wm * 32 + mt * 16 + g + 8 * h;
#pragma unroll
                    for (int jj = 0; jj < 8; jj++) {
                        int n0 = wn * 64 + jj * 8 + 2 * tig;
                        float v0 = c[mt * 8 + jj][2 * h] + bS[n0];
                        float v1 = c[mt * 8 + jj][2 * h + 1] + bS[n0 + 1];
                        *(float2*)(hA + r * 132 + n0) =
                            make_float2(to_tf32(fmaxf(v0, 0.f)), to_tf32(fmaxf(v1, 0.f)));
                    }
                }
        } else {
            // ---- final: bias + LN (2-warp row combine) + residual + scatter ----
            const float* bS = sm + BIAS_F + 2 * H;
            float ps[2][2], pq[2][2];
#pragma unroll
            for (int mt = 0; mt < 2; mt++)
#pragma unroll
                for (int h = 0; h < 2; h++) {
                    float sacc = 0.f, qacc = 0.f;
#pragma unroll
                    for (int jj = 0; jj < 8; jj++) {
                        int n0 = wn * 64 + jj * 8 + 2 * tig;
                        float v0 = c[mt * 8 + jj][2 * h] + bS[n0];
                        float v1 = c[mt * 8 + jj][2 * h + 1] + bS[n0 + 1];
                        c[mt * 8 + jj][2 * h] = v0;
                        c[mt * 8 + jj][2 * h + 1] = v1;
                        sacc += v0 + v1;
                        qacc += v0 * v0 + v1 * v1;
                    }
                    ps[mt][h] = sacc;
                    pq[mt][h] = qacc;
                }
#pragma unroll
            for (int m = 1; m < 4; m <<= 1)
#pragma unroll
                for (int mt = 0; mt < 2; mt++)
#pragma unroll
                    for (int h = 0; h < 2; h++) {
                        ps[mt][h] += __shfl_xor_sync(0xffffffffu, ps[mt][h], m);
                        pq[mt][h] += __shfl_xor_sync(0xffffffffu, pq[mt][h], m);
                    }
            if (tig == 0) {
#pragma unroll
                for (int mt = 0; mt < 2; mt++)
#pragma unroll
                    for (int h = 0; h < 2; h++) {
                        int r = wm * 32 + mt * 16 + g + 8 * h;
                        atomicAdd(&sSum[r], ps[mt][h]);
                        atomicAdd(&sSq[r], pq[mt][h]);
                    }
            }
            __syncthreads();
            const float* gS = sm + BIAS_F + 3 * H;
            const float* eS = sm + BIAS_F + 4 * H;
#pragma unroll
            for (int mt = 0; mt < 2; mt++)
#pragma unroll
                for (int h = 0; h < 2; h++) {
                    int r = wm * 32 + mt * 16 + g + 8 * h;
                    if (r >= nvalid) continue;
                    float mu = sSum[r] * (1.f / H);
                    float rs = rsqrtf(sSq[r] * (1.f / H) - mu * mu + 1e-5f);
                    size_t ro = (size_t)(base + r) * H;
                    int rc = (MODE == 1) ? sR[r] : 0;
#pragma unroll
                    for (int jj = 0; jj < 8; jj++) {
                        int n0 = wn * 64 + jj * 8 + 2 * tig;
                        float y0 = (c[mt * 8 + jj][2 * h] - mu) * rs * gS[n0] + eS[n0];
                        float y1 = (c[mt * 8 + jj][2 * h + 1] - mu) * rs * gS[n0 + 1] + eS[n0 + 1];
                        float2 rf = *(const float2*)(resid + ro + n0);
                        __stcs((float2*)(out + ro + n0), make_float2(y0 + rf.x, y1 + rf.y));
                        if (MODE == 1) red2(&acc[(size_t)rc * H + n0], y0, y1);
                    }
                }
        }
    }
}

// ============================ LAUNCH ============================
extern "C" void kernel_launch(void* const* d_in, const int* in_sizes, int n_in,
                              void* d_out, int out_size) {
    const int*   senders   = (const int*)d_in[0];
    const int*   receivers = (const int*)d_in[1];
    const float* nodef     = (const float*)d_in[2];
    const float* edgef     = (const float*)d_in[3];
    const float* eW0 = (const float*)d_in[4];
    const float* eb0 = (const float*)d_in[5];
    const float* eW1 = (const float*)d_in[6];
    const float* eb1 = (const float*)d_in[7];
    const float* eW2 = (const float*)d_in[8];
    const float* eb2 = (const float*)d_in[9];
    const float* eg  = (const float*)d_in[10];
    const float* ebeta = (const float*)d_in[11];
    const float* nW0 = (const float*)d_in[12];
    const float* nb0 = (const float*)d_in[13];
    const float* nW1 = (const float*)d_in[14];
    const float* nb1 = (const float*)d_in[15];
    const float* nW2 = (const float*)d_in[16];
    const float* nb2 = (const float*)d_in[17];
    const float* ng  = (const float*)d_in[18];
    const float* nbeta = (const float*)d_in[19];

    int E = in_sizes[1];
    int N = in_sizes[2] / H;

    float* out_node = (float*)d_out;
    float* out_edge = out_node + (size_t)N * H;

    float *acc = nullptr, *proj = nullptr;
    cudaGetSymbolAddress((void**)&acc, g_acc);
    cudaGetSymbolAddress((void**)&proj, g_proj);

    cudaFuncSetAttribute(gnb_kernel<0>, cudaFuncAttributeMaxDynamicSharedMemorySize, SMEM_BYTES);
    cudaFuncSetAttribute(gnb_kernel<1>, cudaFuncAttributeMaxDynamicSharedMemorySize, SMEM_BYTES);
    cudaFuncSetAttribute(gnb_kernel<2>, cudaFuncAttributeMaxDynamicSharedMemorySize, SMEM_BYTES);

    int ngrid = (N + TE - 1) / TE;
    int egrid = (E + TE - 1) / TE;

    // proj: P = nodef @ [eW0_send | eW0_recv | nW0_top]
    gnb_kernel<0><<<ngrid, THREADS, SMEM_BYTES>>>(
        nullptr, nullptr, nodef, nullptr, acc, proj,
        eW0, eW0 + (size_t)128 * H, nW0,
        eb0, eb0, eb0, eg, ebeta, nullptr, N);

    // edge MLP: ef @ eW0_bot (+gathered P) -> eW1 -> eW2 -> LN -> scatter
    gnb_kernel<1><<<egrid, THREADS, SMEM_BYTES>>>(
        senders, receivers, nodef, edgef, acc, proj,
        eW0 + (size_t)256 * H, eW1, eW2,
        eb0, eb1, eb2, eg, ebeta, out_edge, E);

    // node MLP: acc @ nW0_bot (+P nf-block) -> nW1 -> nW2 -> LN
    gnb_kernel<2><<<ngrid, THREADS, SMEM_BYTES>>>(
        nullptr, nullptr, nodef, nodef, acc, proj,
        nW0 + (size_t)128 * H, nW1, nW2,
        nb0, nb1, nb2, ng, nbeta, out_node, N);
}

// round 12
// speedup vs baseline: 1.4311x; 1.1864x over previous
#include <cuda_runtime.h>
#include <cstdint>

// GraphNetBlock — mma.sync tf32, v8 (resubmit after infra failure):
//  * W pre-packed in gmem in exact fragment order (repack kernel, tf32-rounded),
//    read via __ldg -> L1-resident. NO smem W, NO staging, NO double buffer.
//  * block-wide __syncthreads: 15 -> 1 per CTA. Inter-stage hA hazards are
//    warp-pair-local -> named pair barriers (bar.sync wm+1, 64).
//  * otherwise v7: proj trick, TE=128, 2 CTAs/SM, 32x64 warp tiles,
//    red.v2 scatter, __stcs stores.

#define H 128
#define TE 128
#define THREADS 256

// float offsets in dynamic smem
#define HA_OFF 0                 // A/hidden: 128 x 132 = 16896
#define BIAS_F 16896             // 5 x 128
#define STAT_F 17536             // sum[128], sq[128]
#define SSR_F  17792             // sS[128], sR[128] ints
#define SMEM_FLOATS 18048
#define SMEM_BYTES (SMEM_FLOATS * 4)   // 72192 -> 2 CTAs/SM, ~83KB L1 left

__device__ float g_acc[50000 * H];
__device__ float g_proj[50000 * 384];
__device__ float4 g_wpk[9 * 4096];   // 9 packed 128x128 weight slices

__device__ __forceinline__ float to_tf32(float x) {
    unsigned u;
    asm("cvt.rna.tf32.f32 %0, %1;" : "=r"(u) : "f"(x));
    return __uint_as_float(u);
}
__device__ __forceinline__ void mma8(float c[4], const unsigned a[4], unsigned b0, unsigned b1) {
    asm volatile(
        "mma.sync.aligned.m16n8k8.row.col.f32.tf32.tf32.f32 "
        "{%0,%1,%2,%3}, {%4,%5,%6,%7}, {%8,%9}, {%0,%1,%2,%3};"
        : "+f"(c[0]), "+f"(c[1]), "+f"(c[2]), "+f"(c[3])
        : "r"(a[0]), "r"(a[1]), "r"(a[2]), "r"(a[3]), "r"(b0), "r"(b1));
}
__device__ __forceinline__ void red2(float* p, float a, float b) {
    asm volatile("red.global.add.v2.f32 [%0], {%1, %2};" :: "l"(p), "f"(a), "f"(b) : "memory");
}
__device__ __forceinline__ void pbar(int id) {
    asm volatile("bar.sync %0, 64;" :: "r"(id) : "memory");
}
__device__ __forceinline__ void zero_c(float c[16][4]) {
#pragma unroll
    for (int j = 0; j < 16; j++)
#pragma unroll
        for (int i = 0; i < 4; i++) c[j][i] = 0.f;
}

// ---- repack: W[k][n] (128x128 slices) -> fragment order, tf32 ----
// out[(((m*16 + k8)*2 + wn)*4 + q)*32 + lane] =
//   {W[k8*8+tig][n0], W[k8*8+tig+4][n0], W[...][n0+8], W[..+4][n0+8]},
//   n0 = wn*64 + q*16 + g,  g = lane>>2, tig = lane&3
__global__ void repack_kernel(const float* __restrict__ eW0, const float* __restrict__ eW1,
                              const float* __restrict__ eW2, const float* __restrict__ nW0,
                              const float* __restrict__ nW1, const float* __restrict__ nW2) {
    int i = blockIdx.x * blockDim.x + threadIdx.x;
    if (i >= 9 * 4096) return;
    int m = i >> 12, r = i & 4095;
    int lane = r & 31, q = (r >> 5) & 3, wn = (r >> 7) & 1, k8 = r >> 8;
    int g = lane >> 2, tig = lane & 3;
    const float* src;
    switch (m) {
        case 0: src = eW0; break;                // eW0_send
        case 1: src = eW0 + 128 * H; break;      // eW0_recv
        case 2: src = nW0; break;                // nW0_top
        case 3: src = eW0 + 256 * H; break;      // eW0_bot
        case 4: src = eW1; break;
        case 5: src = eW2; break;
        case 6: src = nW0 + 128 * H; break;      // nW0_bot
        case 7: src = nW1; break;
        default: src = nW2; break;
    }
    int kq = k8 * 8 + tig;
    int n0 = wn * 64 + q * 16 + g;
    g_wpk[i] = make_float4(to_tf32(src[kq * H + n0]),       to_tf32(src[(kq + 4) * H + n0]),
                           to_tf32(src[kq * H + n0 + 8]),   to_tf32(src[(kq + 4) * H + n0 + 8]));
}

// ---- full K=128 GEMM: A rows from smem (warp owns 32 rows), B via __ldg(L1) ----
__device__ __forceinline__ void mma_K128(float c[16][4], const float* As,
                                         const float4* __restrict__ Wp,
                                         int wm, int wn, int g, int tig, int lane) {
#pragma unroll
    for (int k8 = 0; k8 < 16; k8++) {
        const float4* bp = Wp + ((k8 * 2 + wn) * 4) * 32 + lane;
        float4 bq[4];
        bq[0] = __ldg(bp);
        bq[1] = __ldg(bp + 32);
        bq[2] = __ldg(bp + 64);
        bq[3] = __ldg(bp + 96);
        unsigned a0[4], a1[4];
        const float* ap = As + (wm * 32 + g) * 132 + k8 * 8 + tig;
        a0[0] = __float_as_uint(ap[0]);
        a0[1] = __float_as_uint(ap[8 * 132]);
        a0[2] = __float_as_uint(ap[4]);
        a0[3] = __float_as_uint(ap[8 * 132 + 4]);
        a1[0] = __float_as_uint(ap[16 * 132]);
        a1[1] = __float_as_uint(ap[24 * 132]);
        a1[2] = __float_as_uint(ap[16 * 132 + 4]);
        a1[3] = __float_as_uint(ap[24 * 132 + 4]);
#pragma unroll
        for (int q = 0; q < 4; q++) {
            mma8(c[2 * q],     a0, __float_as_uint(bq[q].x), __float_as_uint(bq[q].y));
            mma8(c[2 * q + 1], a0, __float_as_uint(bq[q].z), __float_as_uint(bq[q].w));
            mma8(c[8 + 2 * q],     a1, __float_as_uint(bq[q].x), __float_as_uint(bq[q].y));
            mma8(c[8 + 2 * q + 1], a1, __float_as_uint(bq[q].z), __float_as_uint(bq[q].w));
        }
    }
}

// ================= unified kernel: MODE 0=proj, 1=edge, 2=node =================
template <int MODE>
__global__ void __launch_bounds__(THREADS, 2)
gnb_kernel(const int* __restrict__ send, const int* __restrict__ recv,
           const float* __restrict__ nodef, const float* __restrict__ resid,
           float* __restrict__ acc, float* __restrict__ proj,
           const float4* __restrict__ Wa, const float4* __restrict__ Wb,
           const float4* __restrict__ Wc,
           const float* __restrict__ pb0, const float* __restrict__ pb1,
           const float* __restrict__ pb2,
           const float* __restrict__ gam, const float* __restrict__ bet,
           float* __restrict__ out, int rows) {
    extern __shared__ float sm[];
    float* hA = sm + HA_OFF;
    float* sSum = sm + STAT_F;
    float* sSq  = sm + STAT_F + 128;
    int* sS = (int*)(sm + SSR_F);
    int* sR = (int*)(sm + SSR_F + 128);

    const int tid = threadIdx.x, lane = tid & 31, warp = tid >> 5;
    const int g = lane >> 2, tig = lane & 3;
    const int wm = warp >> 1, wn = warp & 1;
    const int base = blockIdx.x * TE;
    const int nvalid = min(TE, rows - base);

    // ---- prologue ----
    if (MODE != 0 && tid < H) {
        sm[BIAS_F + 0 * H + tid] = pb0[tid];
        sm[BIAS_F + 1 * H + tid] = pb1[tid];
        sm[BIAS_F + 2 * H + tid] = pb2[tid];
        sm[BIAS_F + 3 * H + tid] = gam[tid];
        sm[BIAS_F + 4 * H + tid] = bet[tid];
    }
    if (MODE != 0 && tid < 128) { sSum[tid] = 0.f; sSq[tid] = 0.f; }
    if (MODE == 1 && tid < TE) {
        int e = min(base + tid, rows - 1);
        sS[tid] = send[e];
        sR[tid] = recv[e];
    }
    // stage A tile (128 x 128, tf32, stride 132)
#pragma unroll
    for (int i = 0; i < 16; i++) {
        int idx4 = tid + (i << 8);
        int r = idx4 >> 5;
        int c4 = (idx4 & 31) << 2;
        int rg = min(base + r, rows - 1);
        float4 v;
        if (MODE == 0) {
            v = *(const float4*)(nodef + (size_t)rg * H + c4);
        } else if (MODE == 1) {
            v = *(const float4*)(resid + (size_t)rg * H + c4);
        } else {
            float4* zp = (float4*)(acc + (size_t)rg * H + c4);
            v = *zp;
            if (base + r < rows) *zp = make_float4(0.f, 0.f, 0.f, 0.f);
        }
        *(float4*)(hA + r * 132 + c4) =
            make_float4(to_tf32(v.x), to_tf32(v.y), to_tf32(v.z), to_tf32(v.w));
    }
    __syncthreads();   // the ONLY block-wide barrier

    float c[16][4];

#pragma unroll 1
    for (int s = 0; s < 3; s++) {
        const float4* Wp = (s == 0) ? Wa : (s == 1) ? Wb : Wc;
        zero_c(c);
        mma_K128(c, hA, Wp, wm, wn, g, tig, lane);

        // ================= epilogues =================
        // c[mt*8 + jj], n0 = wn*64 + jj*8 + 2*tig, rows wm*32 + mt*16 + g + 8h
        if (MODE == 0) {
#pragma unroll
            for (int mt = 0; mt < 2; mt++)
#pragma unroll
                for (int h = 0; h < 2; h++) {
                    int r = wm * 32 + mt * 16 + g + 8 * h;
                    if (r < nvalid) {
                        float* p = proj + (size_t)(base + r) * 384 + s * 128;
#pragma unroll
                        for (int jj = 0; jj < 8; jj++) {
                            int n0 = wn * 64 + jj * 8 + 2 * tig;
                            *(float2*)(p + n0) =
                                make_float2(c[mt * 8 + jj][2 * h], c[mt * 8 + jj][2 * h + 1]);
                        }
                    }
                }
        } else if (s == 0) {
            pbar(1 + wm);   // pair partner done reading hA rows
            const float* bS = sm + BIAS_F;
#pragma unroll
            for (int mt = 0; mt < 2; mt++)
#pragma unroll
                for (int h = 0; h < 2; h++) {
                    int r = wm * 32 + mt * 16 + g + 8 * h;
                    const float* sp;
                    const float* rp = nullptr;
                    if (MODE == 1) {
                        sp = proj + (size_t)sS[r] * 384;
                        rp = proj + (size_t)sR[r] * 384 + 128;
                    } else {
                        sp = proj + (size_t)min(base + r, rows - 1) * 384 + 256;
                    }
#pragma unroll
                    for (int jj = 0; jj < 8; jj++) {
                        int n0 = wn * 64 + jj * 8 + 2 * tig;
                        float2 av = *(const float2*)(sp + n0);
                        float v0 = c[mt * 8 + jj][2 * h] + av.x + bS[n0];
                        float v1 = c[mt * 8 + jj][2 * h + 1] + av.y + bS[n0 + 1];
                        if (MODE == 1) {
                            float2 bv = *(const float2*)(rp + n0);
                            v0 += bv.x;
                            v1 += bv.y;
                        }
                        *(float2*)(hA + r * 132 + n0) =
                            make_float2(to_tf32(fmaxf(v0, 0.f)), to_tf32(fmaxf(v1, 0.f)));
                    }
                }
            pbar(1 + wm);   // pair partner's hA writes visible
        } else if (s == 1) {
            pbar(1 + wm);
            const float* bS = sm + BIAS_F + H;
#pragma unroll
            for (int mt = 0; mt < 2; mt++)
#pragma unroll
                for (int h = 0; h < 2; h++) {
                    int r = wm * 32 + mt * 16 + g + 8 * h;
#pragma unroll
                    for (int jj = 0; jj < 8; jj++) {
                        int n0 = wn * 64 + jj * 8 + 2 * tig;
                        float v0 = c[mt * 8 + jj][2 * h] + bS[n0];
                        float v1 = c[mt * 8 + jj][2 * h + 1] + bS[n0 + 1];
                        *(float2*)(hA + r * 132 + n0) =
                            make_float2(to_tf32(fmaxf(v0, 0.f)), to_tf32(fmaxf(v1, 0.f)));
                    }
                }
            pbar(1 + wm);
        } else {
            // ---- final: bias + LN (pair-combined) + residual + scatter ----
            const float* bS = sm + BIAS_F + 2 * H;
            float ps[2][2], pq[2][2];
#pragma unroll
            for (int mt = 0; mt < 2; mt++)
#pragma unroll
                for (int h = 0; h < 2; h++) {
                    float sacc = 0.f, qacc = 0.f;
#pragma unroll
                    for (int jj = 0; jj < 8; jj++) {
                        int n0 = wn * 64 + jj * 8 + 2 * tig;
                        float v0 = c[mt * 8 + jj][2 * h] + bS[n0];
                        float v1 = c[mt * 8 + jj][2 * h + 1] + bS[n0 + 1];
                        c[mt * 8 + jj][2 * h] = v0;
                        c[mt * 8 + jj][2 * h + 1] = v1;
                        sacc += v0 + v1;
                        qacc += v0 * v0 + v1 * v1;
                    }
                    ps[mt][h] = sacc;
                    pq[mt][h] = qacc;
                }
#pragma unroll
            for (int m = 1; m < 4; m <<= 1)
#pragma unroll
                for (int mt = 0; mt < 2; mt++)
#pragma unroll
                    for (int h = 0; h < 2; h++) {
                        ps[mt][h] += __shfl_xor_sync(0xffffffffu, ps[mt][h], m);
                        pq[mt][h] += __shfl_xor_sync(0xffffffffu, pq[mt][h], m);
                    }
            if (tig == 0) {
#pragma unroll
                for (int mt = 0; mt < 2; mt++)
#pragma unroll
                    for (int h = 0; h < 2; h++) {
                        int r = wm * 32 + mt * 16 + g + 8 * h;
                        atomicAdd(&sSum[r], ps[mt][h]);
                        atomicAdd(&sSq[r], pq[mt][h]);
                    }
            }
            pbar(1 + wm);   // pair stats complete
            const float* gS = sm + BIAS_F + 3 * H;
            const float* eS = sm + BIAS_F + 4 * H;
#pragma unroll
            for (int mt = 0; mt < 2; mt++)
#pragma unroll
                for (int h = 0; h < 2; h++) {
                    int r = wm * 32 + mt * 16 + g + 8 * h;
                    if (r >= nvalid) continue;
                    float mu = sSum[r] * (1.f / H);
                    float rs = rsqrtf(sSq[r] * (1.f / H) - mu * mu + 1e-5f);
                    size_t ro = (size_t)(base + r) * H;
                    int rc = (MODE == 1) ? sR[r] : 0;
#pragma unroll
                    for (int jj = 0; jj < 8; jj++) {
                        int n0 = wn * 64 + jj * 8 + 2 * tig;
                        float y0 = (c[mt * 8 + jj][2 * h] - mu) * rs * gS[n0] + eS[n0];
                        float y1 = (c[mt * 8 + jj][2 * h + 1] - mu) * rs * gS[n0 + 1] + eS[n0 + 1];
                        float2 rf = *(const float2*)(resid + ro + n0);
                        __stcs((float2*)(out + ro + n0), make_float2(y0 + rf.x, y1 + rf.y));
                        if (MODE == 1) red2(&acc[(size_t)rc * H + n0], y0, y1);
                    }
                }
        }
    }
}

// ============================ LAUNCH ============================
extern "C" void kernel_launch(void* const* d_in, const int* in_sizes, int n_in,
                              void* d_out, int out_size) {
    const int*   senders   = (const int*)d_in[0];
    const int*   receivers = (const int*)d_in[1];
    const float* nodef     = (const float*)d_in[2];
    const float* edgef     = (const float*)d_in[3];
    const float* eW0 = (const float*)d_in[4];
    const float* eb0 = (const float*)d_in[5];
    const float* eW1 = (const float*)d_in[6];
    const float* eb1 = (const float*)d_in[7];
    const float* eW2 = (const float*)d_in[8];
    const float* eb2 = (const float*)d_in[9];
    const float* eg  = (const float*)d_in[10];
    const float* ebeta = (const float*)d_in[11];
    const float* nW0 = (const float*)d_in[12];
    const float* nb0 = (const float*)d_in[13];
    const float* nW1 = (const float*)d_in[14];
    const float* nb1 = (const float*)d_in[15];
    const float* nW2 = (const float*)d_in[16];
    const float* nb2 = (const float*)d_in[17];
    const float* ng  = (const float*)d_in[18];
    const float* nbeta = (const float*)d_in[19];

    int E = in_sizes[1];
    int N = in_sizes[2] / H;

    float* out_node = (float*)d_out;
    float* out_edge = out_node + (size_t)N * H;

    float *acc = nullptr, *proj = nullptr;
    float4* wpk = nullptr;
    cudaGetSymbolAddress((void**)&acc, g_acc);
    cudaGetSymbolAddress((void**)&proj, g_proj);
    cudaGetSymbolAddress((void**)&wpk, g_wpk);

    cudaFuncSetAttribute(gnb_kernel<0>, cudaFuncAttributeMaxDynamicSharedMemorySize, SMEM_BYTES);
    cudaFuncSetAttribute(gnb_kernel<1>, cudaFuncAttributeMaxDynamicSharedMemorySize, SMEM_BYTES);
    cudaFuncSetAttribute(gnb_kernel<2>, cudaFuncAttributeMaxDynamicSharedMemorySize, SMEM_BYTES);

    int ngrid = (N + TE - 1) / TE;
    int egrid = (E + TE - 1) / TE;

    repack_kernel<<<(9 * 4096 + 255) / 256, 256>>>(eW0, eW1, eW2, nW0, nW1, nW2);

    // proj: P = nodef @ [eW0_send | eW0_recv | nW0_top]
    gnb_kernel<0><<<ngrid, THREADS, SMEM_BYTES>>>(
        nullptr, nullptr, nodef, nullptr, acc, proj,
        wpk + 0 * 4096, wpk + 1 * 4096, wpk + 2 * 4096,
        eb0, eb0, eb0, eg, ebeta, nullptr, N);

    // edge MLP: ef @ eW0_bot (+gathered P) -> eW1 -> eW2 -> LN -> scatter
    gnb_kernel<1><<<egrid, THREADS, SMEM_BYTES>>>(
        senders, receivers, nodef, edgef, acc, proj,
        wpk + 3 * 4096, wpk + 4 * 4096, wpk + 5 * 4096,
        eb0, eb1, eb2, eg, ebeta, out_edge, E);

    // node MLP: acc @ nW0_bot (+P nf-block) -> nW1 -> nW2 -> LN
    gnb_kernel<2><<<ngrid, THREADS, SMEM_BYTES>>>(
        nullptr, nullptr, nodef, nodef, acc, proj,
        wpk + 6 * 4096, wpk + 7 * 4096, wpk + 8 * 4096,
        nb0, nb1, nb2, ng, nbeta, out_node, N);
}

// round 14
// speedup vs baseline: 1.8682x; 1.3055x over previous
#include <cuda_runtime.h>
#include <cuda_fp16.h>
#include <cstdint>

// GraphNetBlock — mma.sync fp16 (m16n8k16, fp32 accum), v9 (resubmit after infra failure):
//  * fp16 has the SAME 11-bit significand as tf32 -> identical precision,
//    half the mma count, half the operand LDS/LDG traffic, hA smem 66->35KB.
//  * W pre-packed in gmem in exact fp16 fragment order, __ldg from L1.
//  * 1 block-wide barrier + warp-pair named barriers (v8 structure).
//  * proj trick, TE=128, 2 CTAs/SM, 32x64 warp tiles, red.v2 scatter, __stcs.

#define H 128
#define TE 128
#define THREADS 256

// smem: hA = 128 x 136 halves (stride 136 halves -> bank = 4g+tig, conflict-free)
#define HAF 8704                 // hA size in floats (17408 halves)
#define BIAS_F 8704              // 5 x 128 floats
#define STAT_F 9344              // sum[128], sq[128]
#define SSR_F  9600              // sS[128], sR[128] ints
#define SMEM_FLOATS 9856
#define SMEM_BYTES (SMEM_FLOATS * 4)   // 39424 -> 2 CTAs/SM, ~150KB L1 left

__device__ float g_acc[50000 * H];
__device__ float g_proj[50000 * 384];
__device__ float4 g_wpk[9 * 2048];   // 9 packed 128x128 fp16 weight slices (32KB each)

__device__ __forceinline__ unsigned h2u(float lo, float hi) {
    __half2 h = __floats2half2_rn(lo, hi);
    return *(unsigned*)&h;
}
__device__ __forceinline__ void mma16(float c[4], const unsigned a[4], unsigned b0, unsigned b1) {
    asm volatile(
        "mma.sync.aligned.m16n8k16.row.col.f32.f16.f16.f32 "
        "{%0,%1,%2,%3}, {%4,%5,%6,%7}, {%8,%9}, {%0,%1,%2,%3};"
        : "+f"(c[0]), "+f"(c[1]), "+f"(c[2]), "+f"(c[3])
        : "r"(a[0]), "r"(a[1]), "r"(a[2]), "r"(a[3]), "r"(b0), "r"(b1));
}
__device__ __forceinline__ void red2(float* p, float a, float b) {
    asm volatile("red.global.add.v2.f32 [%0], {%1, %2};" :: "l"(p), "f"(a), "f"(b) : "memory");
}
__device__ __forceinline__ void pbar(int id) {
    asm volatile("bar.sync %0, 64;" :: "r"(id) : "memory");
}
__device__ __forceinline__ void zero_c(float c[16][4]) {
#pragma unroll
    for (int j = 0; j < 16; j++)
#pragma unroll
        for (int i = 0; i < 4; i++) c[j][i] = 0.f;
}

// ---- repack: W[k][n] (128x128 slices) -> fp16 fragment order ----
// out[(((m*8 + kk)*2 + wn)*4 + q)*32 + lane] = float4 of half2:
//   x = {W[kb+2tig][n0],   W[kb+2tig+1][n0]}     (b0 for n-tile 2q)
//   y = {W[kb+2tig+8][n0], W[kb+2tig+9][n0]}     (b1 for n-tile 2q)
//   z,w = same at n0+8                            (n-tile 2q+1)
//   kb = kk*16, n0 = wn*64 + q*16 + g, g = lane>>2, tig = lane&3
__global__ void repack_kernel(const float* __restrict__ eW0, const float* __restrict__ eW1,
                              const float* __restrict__ eW2, const float* __restrict__ nW0,
                              const float* __restrict__ nW1, const float* __restrict__ nW2) {
    int i = blockIdx.x * blockDim.x + threadIdx.x;
    if (i >= 9 * 2048) return;
    int m = i >> 11, r = i & 2047;
    int lane = r & 31, q = (r >> 5) & 3, wn = (r >> 7) & 1, kk = r >> 8;
    int g = lane >> 2, tig = lane & 3;
    const float* src;
    switch (m) {
        case 0: src = eW0; break;                // eW0_send
        case 1: src = eW0 + 128 * H; break;      // eW0_recv
        case 2: src = nW0; break;                // nW0_top
        case 3: src = eW0 + 256 * H; break;      // eW0_bot
        case 4: src = eW1; break;
        case 5: src = eW2; break;
        case 6: src = nW0 + 128 * H; break;      // nW0_bot
        case 7: src = nW1; break;
        default: src = nW2; break;
    }
    int kb = kk * 16 + 2 * tig;
    int n0 = wn * 64 + q * 16 + g;
    float4 o;
    *(unsigned*)&o.x = h2u(src[kb * H + n0],       src[(kb + 1) * H + n0]);
    *(unsigned*)&o.y = h2u(src[(kb + 8) * H + n0], src[(kb + 9) * H + n0]);
    *(unsigned*)&o.z = h2u(src[kb * H + n0 + 8],       src[(kb + 1) * H + n0 + 8]);
    *(unsigned*)&o.w = h2u(src[(kb + 8) * H + n0 + 8], src[(kb + 9) * H + n0 + 8]);
    g_wpk[i] = o;
}

// ---- full K=128 fp16 GEMM: A (half, stride 136) from smem, B via __ldg(L1) ----
__device__ __forceinline__ void mma_K128(float c[16][4], const __half* As,
                                         const float4* __restrict__ Wp,
                                         int wm, int wn, int g, int tig, int lane) {
#pragma unroll
    for (int kk = 0; kk < 8; kk++) {
        const float4* bp = Wp + ((kk * 2 + wn) * 4) * 32 + lane;
        float4 bq[4];
        bq[0] = __ldg(bp);
        bq[1] = __ldg(bp + 32);
        bq[2] = __ldg(bp + 64);
        bq[3] = __ldg(bp + 96);
        unsigned a0[4], a1[4];
        const __half* ap = As + (wm * 32 + g) * 136 + kk * 16 + 2 * tig;
        a0[0] = *(const unsigned*)(ap);
        a0[1] = *(const unsigned*)(ap + 8 * 136);
        a0[2] = *(const unsigned*)(ap + 8);
        a0[3] = *(const unsigned*)(ap + 8 * 136 + 8);
        a1[0] = *(const unsigned*)(ap + 16 * 136);
        a1[1] = *(const unsigned*)(ap + 24 * 136);
        a1[2] = *(const unsigned*)(ap + 16 * 136 + 8);
        a1[3] = *(const unsigned*)(ap + 24 * 136 + 8);
#pragma unroll
        for (int q = 0; q < 4; q++) {
            unsigned bx = *(const unsigned*)&bq[q].x, by = *(const unsigned*)&bq[q].y;
            unsigned bz = *(const unsigned*)&bq[q].z, bw = *(const unsigned*)&bq[q].w;
            mma16(c[2 * q],     a0, bx, by);
            mma16(c[2 * q + 1], a0, bz, bw);
            mma16(c[8 + 2 * q],     a1, bx, by);
            mma16(c[8 + 2 * q + 1], a1, bz, bw);
        }
    }
}

// ================= unified kernel: MODE 0=proj, 1=edge, 2=node =================
template <int MODE>
__global__ void __launch_bounds__(THREADS, 2)
gnb_kernel(const int* __restrict__ send, const int* __restrict__ recv,
           const float* __restrict__ nodef, const float* __restrict__ resid,
           float* __restrict__ acc, float* __restrict__ proj,
           const float4* __restrict__ Wa, const float4* __restrict__ Wb,
           const float4* __restrict__ Wc,
           const float* __restrict__ pb0, const float* __restrict__ pb1,
           const float* __restrict__ pb2,
           const float* __restrict__ gam, const float* __restrict__ bet,
           float* __restrict__ out, int rows) {
    extern __shared__ float sm[];
    __half* hA = (__half*)sm;                 // 128 x 136 halves
    float* sSum = sm + STAT_F;
    float* sSq  = sm + STAT_F + 128;
    int* sS = (int*)(sm + SSR_F);
    int* sR = (int*)(sm + SSR_F + 128);

    const int tid = threadIdx.x, lane = tid & 31, warp = tid >> 5;
    const int g = lane >> 2, tig = lane & 3;
    const int wm = warp >> 1, wn = warp & 1;
    const int base = blockIdx.x * TE;
    const int nvalid = min(TE, rows - base);

    // ---- prologue ----
    if (MODE != 0 && tid < H) {
        sm[BIAS_F + 0 * H + tid] = pb0[tid];
        sm[BIAS_F + 1 * H + tid] = pb1[tid];
        sm[BIAS_F + 2 * H + tid] = pb2[tid];
        sm[BIAS_F + 3 * H + tid] = gam[tid];
        sm[BIAS_F + 4 * H + tid] = bet[tid];
    }
    if (MODE != 0 && tid < 128) { sSum[tid] = 0.f; sSq[tid] = 0.f; }
    if (MODE == 1 && tid < TE) {
        int e = min(base + tid, rows - 1);
        sS[tid] = send[e];
        sR[tid] = recv[e];
    }
    // stage A tile (128 x 128 -> fp16, stride 136 halves)
#pragma unroll
    for (int i = 0; i < 16; i++) {
        int idx4 = tid + (i << 8);
        int r = idx4 >> 5;
        int c4 = (idx4 & 31) << 2;
        int rg = min(base + r, rows - 1);
        float4 v;
        if (MODE == 0) {
            v = *(const float4*)(nodef + (size_t)rg * H + c4);
        } else if (MODE == 1) {
            v = *(const float4*)(resid + (size_t)rg * H + c4);
        } else {
            float4* zp = (float4*)(acc + (size_t)rg * H + c4);
            v = *zp;
            if (base + r < rows) *zp = make_float4(0.f, 0.f, 0.f, 0.f);
        }
        uint2 pk;
        pk.x = h2u(v.x, v.y);
        pk.y = h2u(v.z, v.w);
        *(uint2*)(hA + r * 136 + c4) = pk;
    }
    __syncthreads();   // the ONLY block-wide barrier

    float c[16][4];

#pragma unroll 1
    for (int s = 0; s < 3; s++) {
        const float4* Wp = (s == 0) ? Wa : (s == 1) ? Wb : Wc;
        zero_c(c);
        mma_K128(c, hA, Wp, wm, wn, g, tig, lane);

        // ================= epilogues =================
        // c[mt*8 + jj], n0 = wn*64 + jj*8 + 2*tig, rows wm*32 + mt*16 + g + 8h
        if (MODE == 0) {
#pragma unroll
            for (int mt = 0; mt < 2; mt++)
#pragma unroll
                for (int h = 0; h < 2; h++) {
                    int r = wm * 32 + mt * 16 + g + 8 * h;
                    if (r < nvalid) {
                        float* p = proj + (size_t)(base + r) * 384 + s * 128;
#pragma unroll
                        for (int jj = 0; jj < 8; jj++) {
                            int n0 = wn * 64 + jj * 8 + 2 * tig;
                            *(float2*)(p + n0) =
                                make_float2(c[mt * 8 + jj][2 * h], c[mt * 8 + jj][2 * h + 1]);
                        }
                    }
                }
        } else if (s == 0) {
            pbar(1 + wm);   // pair partner done reading hA rows
            const float* bS = sm + BIAS_F;
#pragma unroll
            for (int mt = 0; mt < 2; mt++)
#pragma unroll
                for (int h = 0; h < 2; h++) {
                    int r = wm * 32 + mt * 16 + g + 8 * h;
                    const float* sp;
                    const float* rp = nullptr;
                    if (MODE == 1) {
                        sp = proj + (size_t)sS[r] * 384;
                        rp = proj + (size_t)sR[r] * 384 + 128;
                    } else {
                        sp = proj + (size_t)min(base + r, rows - 1) * 384 + 256;
                    }
#pragma unroll
                    for (int jj = 0; jj < 8; jj++) {
                        int n0 = wn * 64 + jj * 8 + 2 * tig;
                        float2 av = *(const float2*)(sp + n0);
                        float v0 = c[mt * 8 + jj][2 * h] + av.x + bS[n0];
                        float v1 = c[mt * 8 + jj][2 * h + 1] + av.y + bS[n0 + 1];
                        if (MODE == 1) {
                            float2 bv = *(const float2*)(rp + n0);
                            v0 += bv.x;
                            v1 += bv.y;
                        }
                        *(unsigned*)(hA + r * 136 + n0) =
                            h2u(fmaxf(v0, 0.f), fmaxf(v1, 0.f));
                    }
                }
            pbar(1 + wm);   // pair partner's hA writes visible
        } else if (s == 1) {
            pbar(1 + wm);
            const float* bS = sm + BIAS_F + H;
#pragma unroll
            for (int mt = 0; mt < 2; mt++)
#pragma unroll
                for (int h = 0; h < 2; h++) {
                    int r = wm * 32 + mt * 16 + g + 8 * h;
#pragma unroll
                    for (int jj = 0; jj < 8; jj++) {
                        int n0 = wn * 64 + jj * 8 + 2 * tig;
                        float v0 = c[mt * 8 + jj][2 * h] + bS[n0];
                        float v1 = c[mt * 8 + jj][2 * h + 1] + bS[n0 + 1];
                        *(unsigned*)(hA + r * 136 + n0) =
                            h2u(fmaxf(v0, 0.f), fmaxf(v1, 0.f));
                    }
                }
            pbar(1 + wm);
        } else {
            // ---- final: bias + LN (pair-combined) + residual + scatter ----
            const float* bS = sm + BIAS_F + 2 * H;
            float ps[2][2], pq[2][2];
#pragma unroll
            for (int mt = 0; mt < 2; mt++)
#pragma unroll
                for (int h = 0; h < 2; h++) {
                    float sacc = 0.f, qacc = 0.f;
#pragma unroll
                    for (int jj = 0; jj < 8; jj++) {
                        int n0 = wn * 64 + jj * 8 + 2 * tig;
                        float v0 = c[mt * 8 + jj][2 * h] + bS[n0];
                        float v1 = c[mt * 8 + jj][2 * h + 1] + bS[n0 + 1];
                        c[mt * 8 + jj][2 * h] = v0;
                        c[mt * 8 + jj][2 * h + 1] = v1;
                        sacc += v0 + v1;
                        qacc += v0 * v0 + v1 * v1;
                    }
                    ps[mt][h] = sacc;
                    pq[mt][h] = qacc;
                }
#pragma unroll
            for (int m = 1; m < 4; m <<= 1)
#pragma unroll
                for (int mt = 0; mt < 2; mt++)
#pragma unroll
                    for (int h = 0; h < 2; h++) {
                        ps[mt][h] += __shfl_xor_sync(0xffffffffu, ps[mt][h], m);
                        pq[mt][h] += __shfl_xor_sync(0xffffffffu, pq[mt][h], m);
                    }
            if (tig == 0) {
#pragma unroll
                for (int mt = 0; mt < 2; mt++)
#pragma unroll
                    for (int h = 0; h < 2; h++) {
                        int r = wm * 32 + mt * 16 + g + 8 * h;
                        atomicAdd(&sSum[r], ps[mt][h]);
                        atomicAdd(&sSq[r], pq[mt][h]);
                    }
            }
            pbar(1 + wm);   // pair stats complete
            const float* gS = sm + BIAS_F + 3 * H;
            const float* eS = sm + BIAS_F + 4 * H;
#pragma unroll
            for (int mt = 0; mt < 2; mt++)
#pragma unroll
                for (int h = 0; h < 2; h++) {
                    int r = wm * 32 + mt * 16 + g + 8 * h;
                    if (r >= nvalid) continue;
                    float mu = sSum[r] * (1.f / H);
                    float rs = rsqrtf(sSq[r] * (1.f / H) - mu * mu + 1e-5f);
                    size_t ro = (size_t)(base + r) * H;
                    int rc = (MODE == 1) ? sR[r] : 0;
#pragma unroll
                    for (int jj = 0; jj < 8; jj++) {
                        int n0 = wn * 64 + jj * 8 + 2 * tig;
                        float y0 = (c[mt * 8 + jj][2 * h] - mu) * rs * gS[n0] + eS[n0];
                        float y1 = (c[mt * 8 + jj][2 * h + 1] - mu) * rs * gS[n0 + 1] + eS[n0 + 1];
                        float2 rf = *(const float2*)(resid + ro + n0);
                        __stcs((float2*)(out + ro + n0), make_float2(y0 + rf.x, y1 + rf.y));
                        if (MODE == 1) red2(&acc[(size_t)rc * H + n0], y0, y1);
                    }
                }
        }
    }
}

// ============================ LAUNCH ============================
extern "C" void kernel_launch(void* const* d_in, const int* in_sizes, int n_in,
                              void* d_out, int out_size) {
    const int*   senders   = (const int*)d_in[0];
    const int*   receivers = (const int*)d_in[1];
    const float* nodef     = (const float*)d_in[2];
    const float* edgef     = (const float*)d_in[3];
    const float* eW0 = (const float*)d_in[4];
    const float* eb0 = (const float*)d_in[5];
    const float* eW1 = (const float*)d_in[6];
    const float* eb1 = (const float*)d_in[7];
    const float* eW2 = (const float*)d_in[8];
    const float* eb2 = (const float*)d_in[9];
    const float* eg  = (const float*)d_in[10];
    const float* ebeta = (const float*)d_in[11];
    const float* nW0 = (const float*)d_in[12];
    const float* nb0 = (const float*)d_in[13];
    const float* nW1 = (const float*)d_in[14];
    const float* nb1 = (const float*)d_in[15];
    const float* nW2 = (const float*)d_in[16];
    const float* nb2 = (const float*)d_in[17];
    const float* ng  = (const float*)d_in[18];
    const float* nbeta = (const float*)d_in[19];

    int E = in_sizes[1];
    int N = in_sizes[2] / H;

    float* out_node = (float*)d_out;
    float* out_edge = out_node + (size_t)N * H;

    float *acc = nullptr, *proj = nullptr;
    float4* wpk = nullptr;
    cudaGetSymbolAddress((void**)&acc, g_acc);
    cudaGetSymbolAddress((void**)&proj, g_proj);
    cudaGetSymbolAddress((void**)&wpk, g_wpk);

    cudaFuncSetAttribute(gnb_kernel<0>, cudaFuncAttributeMaxDynamicSharedMemorySize, SMEM_BYTES);
    cudaFuncSetAttribute(gnb_kernel<1>, cudaFuncAttributeMaxDynamicSharedMemorySize, SMEM_BYTES);
    cudaFuncSetAttribute(gnb_kernel<2>, cudaFuncAttributeMaxDynamicSharedMemorySize, SMEM_BYTES);

    int ngrid = (N + TE - 1) / TE;
    int egrid = (E + TE - 1) / TE;

    repack_kernel<<<(9 * 2048 + 255) / 256, 256>>>(eW0, eW1, eW2, nW0, nW1, nW2);

    // proj: P = nodef @ [eW0_send | eW0_recv | nW0_top]
    gnb_kernel<0><<<ngrid, THREADS, SMEM_BYTES>>>(
        nullptr, nullptr, nodef, nullptr, acc, proj,
        wpk + 0 * 2048, wpk + 1 * 2048, wpk + 2 * 2048,
        eb0, eb0, eb0, eg, ebeta, nullptr, N);

    // edge MLP: ef @ eW0_bot (+gathered P) -> eW1 -> eW2 -> LN -> scatter
    gnb_kernel<1><<<egrid, THREADS, SMEM_BYTES>>>(
        senders, receivers, nodef, edgef, acc, proj,
        wpk + 3 * 2048, wpk + 4 * 2048, wpk + 5 * 2048,
        eb0, eb1, eb2, eg, ebeta, out_edge, E);

    // node MLP: acc @ nW0_bot (+P nf-block) -> nW1 -> nW2 -> LN
    gnb_kernel<2><<<ngrid, THREADS, SMEM_BYTES>>>(
        nullptr, nullptr, nodef, nodef, acc, proj,
        wpk + 6 * 2048, wpk + 7 * 2048, wpk + 8 * 2048,
        nb0, nb1, nb2, ng, nbeta, out_node, N);
}